// round 1
// baseline (speedup 1.0000x reference)
#include <cuda_runtime.h>
#include <math.h>

// Real spherical harmonics Y_{l,m}, l_max = 8, output [N, 81] fp32.
// Store-bound kernel: compute per-thread, transpose through smem, flush
// with coalesced float4 stores.

namespace {
constexpr int LMAX  = 8;
constexpr int NCOLS = (LMAX + 1) * (LMAX + 1);  // 81
constexpr int BLK   = 128;
constexpr int PADW  = BLK + 1;                  // 129, gcd(129,32)=1 -> conflict-free

struct KTab { float v[LMAX + 1][LMAX + 1]; };

constexpr double cfact(int n) {
    double r = 1.0;
    for (int i = 2; i <= n; ++i) r *= (double)i;
    return r;
}
// constexpr Newton sqrt (double)
constexpr double csqrtd(double x) {
    double g = (x > 1.0) ? x : 1.0;
    for (int i = 0; i < 64; ++i) g = 0.5 * (g + x / g);
    return g;
}
constexpr double CPI = 3.14159265358979323846264338327950288;

constexpr KTab makeK() {
    KTab t{};
    for (int l = 0; l <= LMAX; ++l) {
        for (int m = 0; m <= l; ++m) {
            double k = csqrtd(((2.0 * l + 1.0) / (4.0 * CPI)) *
                              (cfact(l - m) / cfact(l + m)));
            if (m > 0) k *= csqrtd(2.0);  // fold sqrt(2) for m != 0
            t.v[l][m] = (float)k;
        }
    }
    return t;
}
}  // namespace

__constant__ KTab KT = makeK();  // static (constexpr) init — no dynamic init, legal

__global__ void __launch_bounds__(BLK)
sh_kernel(const float* __restrict__ ct_in,
          const float* __restrict__ ph_in,
          float* __restrict__ out, int n)
{
    __shared__ float s[NCOLS][PADW];  // s[col][tid], padded

    const int t    = threadIdx.x;
    const int base = blockIdx.x * BLK;
    const int i    = base + t;

    float ct = 0.0f, ph = 0.0f;
    if (i < n) { ct = ct_in[i]; ph = ph_in[i]; }

    float st = sqrtf(fmaxf(1.0f - ct * ct, 0.0f));
    float sp, cp;
    __sincosf(ph, &sp, &cp);

    float cm  = 1.0f;  // cos(m*phi)
    float smv = 0.0f;  // sin(m*phi)
    float pmm = 1.0f;  // P(m,m)

#pragma unroll
    for (int m = 0; m <= LMAX; ++m) {
        if (m > 0) {
            float c2 = cm * cp - smv * sp;
            float s2 = smv * cp + cm * sp;
            cm = c2; smv = s2;
            pmm *= st * (float)(2 * m - 1);   // P(m,m) = P(m-1,m-1)*st*(2m-1)
        }

        // l = m
        float Pa = pmm;
        {
            const float k = KT.v[m][m];
            const int c0 = m * m + m;         // l*l + l, l = m
            if (m == 0) {
                s[c0][t] = k * Pa;
            } else {
                float kp = k * Pa;
                s[c0 + m][t] = kp * cm;
                s[c0 - m][t] = kp * smv;
            }
        }

        if (m < LMAX) {
            // l = m+1:  P(m+1,m) = ct*(2m+1)*P(m,m)
            float Pb = ct * (float)(2 * m + 1) * Pa;
            {
                const int l  = m + 1;
                const float k = KT.v[l][m];
                const int c0 = l * l + l;
                if (m == 0) {
                    s[c0][t] = k * Pb;
                } else {
                    float kp = k * Pb;
                    s[c0 + m][t] = kp * cm;
                    s[c0 - m][t] = kp * smv;
                }
            }
#pragma unroll
            for (int l = m + 2; l <= LMAX; ++l) {
                // P(l,m) = ((2l-1)*ct*P(l-1,m) - (l+m-1)*P(l-2,m)) / (l-m)
                float Pc = ((float)(2 * l - 1) * ct * Pb -
                            (float)(l + m - 1) * Pa) * (1.0f / (float)(l - m));
                const float k = KT.v[l][m];
                const int c0 = l * l + l;
                if (m == 0) {
                    s[c0][t] = k * Pc;
                } else {
                    float kp = k * Pc;
                    s[c0 + m][t] = kp * cm;
                    s[c0 - m][t] = kp * smv;
                }
                Pa = Pb; Pb = Pc;
            }
        }
    }

    __syncthreads();

    // Flush: the block's output region is fully contiguous:
    // out[base*81 .. (base+npts)*81)
    float* dst = out + (size_t)base * NCOLS;
    int npts = n - base;
    if (npts > BLK) npts = BLK;

    if (npts == BLK) {
        // 128*81 = 10368 floats = 2592 float4, coalesced STG.128
        constexpr int NQ = (BLK * NCOLS) / 4;  // 2592
        for (int q = t; q < NQ; q += BLK) {
            int f = q * 4;
            float4 v;
            v.x = s[(f    ) % NCOLS][(f    ) / NCOLS];
            v.y = s[(f + 1) % NCOLS][(f + 1) / NCOLS];
            v.z = s[(f + 2) % NCOLS][(f + 2) / NCOLS];
            v.w = s[(f + 3) % NCOLS][(f + 3) / NCOLS];
            reinterpret_cast<float4*>(dst)[q] = v;
        }
    } else if (npts > 0) {
        int total = npts * NCOLS;
        for (int f = t; f < total; f += BLK) {
            dst[f] = s[f % NCOLS][f / NCOLS];
        }
    }
}

extern "C" void kernel_launch(void* const* d_in, const int* in_sizes, int n_in,
                              void* d_out, int out_size)
{
    // Inputs in metadata order: l_max (scalar), cos_theta [N], phi [N].
    // Be robust to whether the scalar is materialized as an input.
    int ia = (n_in >= 3) ? 1 : 0;
    const float* ct = (const float*)d_in[ia];
    const float* ph = (const float*)d_in[ia + 1];

    int n = out_size / NCOLS;  // definitive N from output element count
    if (n <= 0) return;

    int grid = (n + BLK - 1) / BLK;
    sh_kernel<<<grid, BLK>>>(ct, ph, (float*)d_out, n);
}

// round 2
// speedup vs baseline: 1.4457x; 1.4457x over previous
#include <cuda_runtime.h>
#include <math.h>

// Real spherical harmonics Y_{l,m}, l_max = 8, output [N, 81] fp32.
// Store-bound. Compute per-thread, stage in smem in OUTPUT order
// (row-major per point, stride 81; 81 mod 32 = 17 is coprime with 32 so
// column-wise STS are conflict-free), flush with contiguous LDS.128 +
// coalesced streaming STG.128.

namespace {
constexpr int LMAX  = 8;
constexpr int NCOLS = (LMAX + 1) * (LMAX + 1);  // 81
constexpr int BLK   = 128;

struct KTab { float v[LMAX + 1][LMAX + 1]; };

constexpr double cfact(int n) {
    double r = 1.0;
    for (int i = 2; i <= n; ++i) r *= (double)i;
    return r;
}
constexpr double csqrtd(double x) {
    double g = (x > 1.0) ? x : 1.0;
    for (int i = 0; i < 64; ++i) g = 0.5 * (g + x / g);
    return g;
}
constexpr double CPI = 3.14159265358979323846264338327950288;

constexpr KTab makeK() {
    KTab t{};
    for (int l = 0; l <= LMAX; ++l) {
        for (int m = 0; m <= l; ++m) {
            double k = csqrtd(((2.0 * l + 1.0) / (4.0 * CPI)) *
                              (cfact(l - m) / cfact(l + m)));
            if (m > 0) k *= csqrtd(2.0);  // fold sqrt(2) for m != 0
            t.v[l][m] = (float)k;
        }
    }
    return t;
}
}  // namespace

__constant__ KTab KT = makeK();

__global__ void __launch_bounds__(BLK)
sh_kernel(const float* __restrict__ ct_in,
          const float* __restrict__ ph_in,
          float* __restrict__ out, int n)
{
    // Output-order staging: s[t*81 + c]. No padding; stride 81 is coprime
    // with 32 banks, so per-column STS across lanes are conflict-free.
    __shared__ float s[BLK * NCOLS];  // 41472 B

    const int t    = threadIdx.x;
    const int base = blockIdx.x * BLK;
    const int i    = base + t;

    float ct = 0.0f, ph = 0.0f;
    if (i < n) { ct = ct_in[i]; ph = ph_in[i]; }

    float st = sqrtf(fmaxf(1.0f - ct * ct, 0.0f));
    float sp, cp;
    __sincosf(ph, &sp, &cp);

    float* row = s + t * NCOLS;

    float cm  = 1.0f;  // cos(m*phi)
    float smv = 0.0f;  // sin(m*phi)
    float pmm = 1.0f;  // P(m,m)

#pragma unroll
    for (int m = 0; m <= LMAX; ++m) {
        if (m > 0) {
            float c2 = cm * cp - smv * sp;
            float s2 = smv * cp + cm * sp;
            cm = c2; smv = s2;
            pmm *= st * (float)(2 * m - 1);   // P(m,m)
        }

        float Pa = pmm;  // l = m
        {
            const float k = KT.v[m][m];
            const int c0 = m * m + m;
            if (m == 0) {
                row[c0] = k * Pa;
            } else {
                float kp = k * Pa;
                row[c0 + m] = kp * cm;
                row[c0 - m] = kp * smv;
            }
        }

        if (m < LMAX) {
            float Pb = ct * (float)(2 * m + 1) * Pa;  // l = m+1
            {
                const int l  = m + 1;
                const float k = KT.v[l][m];
                const int c0 = l * l + l;
                if (m == 0) {
                    row[c0] = k * Pb;
                } else {
                    float kp = k * Pb;
                    row[c0 + m] = kp * cm;
                    row[c0 - m] = kp * smv;
                }
            }
#pragma unroll
            for (int l = m + 2; l <= LMAX; ++l) {
                float Pc = ((float)(2 * l - 1) * ct * Pb -
                            (float)(l + m - 1) * Pa) * (1.0f / (float)(l - m));
                const float k = KT.v[l][m];
                const int c0 = l * l + l;
                if (m == 0) {
                    row[c0] = k * Pc;
                } else {
                    float kp = k * Pc;
                    row[c0 + m] = kp * cm;
                    row[c0 - m] = kp * smv;
                }
                Pa = Pb; Pb = Pc;
            }
        }
    }

    __syncthreads();

    // Flush: block's region is contiguous in gmem AND in smem.
    float* dst = out + (size_t)base * NCOLS;
    int npts = n - base;
    if (npts > BLK) npts = BLK;

    if (npts == BLK) {
        constexpr int NQ = (BLK * NCOLS) / 4;  // 2592 float4
        const float4* s4 = reinterpret_cast<const float4*>(s);
        float4* d4 = reinterpret_cast<float4*>(dst);
#pragma unroll 4
        for (int q = t; q < NQ; q += BLK) {
            __stcs(d4 + q, s4[q]);   // streaming: no L2 pollution, write-once
        }
    } else if (npts > 0) {
        int total = npts * NCOLS;
        for (int f = t; f < total; f += BLK) {
            __stcs(dst + f, s[f]);
        }
    }
}

extern "C" void kernel_launch(void* const* d_in, const int* in_sizes, int n_in,
                              void* d_out, int out_size)
{
    int ia = (n_in >= 3) ? 1 : 0;
    const float* ct = (const float*)d_in[ia];
    const float* ph = (const float*)d_in[ia + 1];

    int n = out_size / NCOLS;
    if (n <= 0) return;

    int grid = (n + BLK - 1) / BLK;
    sh_kernel<<<grid, BLK>>>(ct, ph, (float*)d_out, n);
}